// round 15
// baseline (speedup 1.0000x reference)
#include <cuda_runtime.h>
#include <cuda_fp16.h>
#include <cstdint>

// Problem dims
#define BB   128
#define TT   256
#define FF   64
#define UU   1024
#define G4   4096
#define OUTS 32
#define DH   32
#define KENC 1088      // F + U -> 17 chunks of K=64
#define KRNN 2048      // U + U -> 32 chunks
#define NB   128       // persistent grid size
#define NT   384       // threads: 3 groups x 4 warps

// Dynamic smem layout (bytes), all tiles 64 rows x 128B, XOR-swizzled
#define SW_OFF 0                        // 17 x 8192 resident W / decoder B rings
#define SA_OFF (17 * 8192)              // 139264: 9 x 8192 A rings (3 per group)
#define DYN_BYTES (SA_OFF + 9 * 8192)   // 212992

#define SWZ(o) ((o) ^ (((o) >> 3) & 0x70))

// ------------------------- device scratch -----------------------------------
__device__ __align__(16) __half g_XF16[(size_t)TT * BB * FF];  // [t][b][f]
__device__ __align__(16) __half g_Wenc[(size_t)KENC * G4];     // [k][n'], n'=u*4+gate
__device__ __align__(16) __half g_Wcell[(size_t)KENC * G4];
__device__ __align__(16) __half g_Wrnn[(size_t)KRNN * G4];
__device__ float g_benc[G4], g_bcell[G4], g_brnn[G4];
__device__ float g_Hl[BB * UU], g_Hr[BB * UU];
__device__ __align__(16) __half g_H16[2][BB * UU];
__device__ __align__(16) __half g_HR16[2][BB * UU];
__device__ __align__(16) __half g_P16[BB * FF];
__device__ unsigned long long g_tick = 0ull;

// ------------------------- PTX helpers --------------------------------------
__device__ __forceinline__ void cp16u(uint32_t s, const void* g) {
    asm volatile("cp.async.cg.shared.global [%0], [%1], 16;" :: "r"(s), "l"(g));
}
__device__ __forceinline__ void cp_commit() { asm volatile("cp.async.commit_group;"); }
template<int N> __device__ __forceinline__ void cp_wait() {
    asm volatile("cp.async.wait_group %0;" :: "n"(N));
}
__device__ __forceinline__ void bar_named(int id) {
    asm volatile("bar.sync %0, 128;" :: "r"(id) : "memory");
}
__device__ __forceinline__ void ldsm_x4(uint32_t* r, uint32_t a) {
    asm volatile("ldmatrix.sync.aligned.m8n8.x4.shared.b16 {%0,%1,%2,%3}, [%4];"
                 : "=r"(r[0]), "=r"(r[1]), "=r"(r[2]), "=r"(r[3]) : "r"(a));
}
__device__ __forceinline__ void ldsm_x2t(uint32_t* r, uint32_t a) {
    asm volatile("ldmatrix.sync.aligned.m8n8.x2.trans.shared.b16 {%0,%1}, [%2];"
                 : "=r"(r[0]), "=r"(r[1]) : "r"(a));
}
__device__ __forceinline__ void mma16816(float* c, const uint32_t* a, const uint32_t* b) {
    asm volatile(
        "mma.sync.aligned.m16n8k16.row.col.f32.f16.f16.f32 "
        "{%0,%1,%2,%3}, {%4,%5,%6,%7}, {%8,%9}, {%0,%1,%2,%3};"
        : "+f"(c[0]), "+f"(c[1]), "+f"(c[2]), "+f"(c[3])
        : "r"(a[0]), "r"(a[1]), "r"(a[2]), "r"(a[3]), "r"(b[0]), "r"(b[1]));
}
__device__ __forceinline__ float sigmoidf_fast(float x) {
    return 1.0f / (1.0f + __expf(-x));
}

// Grid barrier: monotone ticket (replay-safe).
__device__ __forceinline__ void grid_barrier(unsigned long long& base, int& cnt) {
    __threadfence();
    __syncthreads();
    if (threadIdx.x == 0) {
        if (cnt == 0) {
            unsigned long long v = atomicAdd(&g_tick, 1ull);
            base = (v / NB) * NB;
        } else {
            atomicAdd(&g_tick, 1ull);
        }
        cnt++;
        unsigned long long target = base + (unsigned long long)cnt * NB;
        while (*(volatile unsigned long long*)&g_tick < target) __nanosleep(16);
        __threadfence();
    }
    __syncthreads();
}

// ------------------------- merged prep kernel --------------------------------
__global__ void prep_all(
    const float* __restrict__ Wl, const float* __restrict__ Rl, const float* __restrict__ bl,
    const float* __restrict__ Wc, const float* __restrict__ Rc, const float* __restrict__ bc,
    const float* __restrict__ Wr, const float* __restrict__ Rr, const float* __restrict__ br,
    const float* __restrict__ x)
{
    size_t idx = (size_t)blockIdx.x * 256 + threadIdx.x;
    const size_t NENC  = (size_t)KENC * G4;
    const size_t NRNN  = (size_t)KRNN * G4;
    const size_t NCONV = (size_t)TT * BB * FF;

    if (idx < NENC) {
        size_t k = idx >> 12; int np = (int)(idx & 4095);
        int u = np >> 2, gate = np & 3, col = gate * UU + u;
        float v = (k < FF) ? Wl[k * G4 + col] : Rl[(k - FF) * G4 + col];
        g_Wenc[idx] = __float2half_rn(v);
        return;
    }
    idx -= NENC;
    if (idx < NENC) {
        size_t k = idx >> 12; int np = (int)(idx & 4095);
        int u = np >> 2, gate = np & 3, col = gate * UU + u;
        float v = (k < FF) ? Wc[k * G4 + col] : Rc[(k - FF) * G4 + col];
        g_Wcell[idx] = __float2half_rn(v);
        return;
    }
    idx -= NENC;
    if (idx < NRNN) {
        size_t k = idx >> 12; int np = (int)(idx & 4095);
        int u = np >> 2, gate = np & 3, col = gate * UU + u;
        float v = (k < UU) ? Wr[k * G4 + col] : Rr[(k - UU) * G4 + col];
        g_Wrnn[idx] = __float2half_rn(v);
        return;
    }
    idx -= NRNN;
    if (idx < NCONV) {
        size_t t = idx / (BB * FF);
        int r = (int)(idx % (BB * FF));
        int b = r / FF, f = r % FF;
        g_XF16[idx] = __float2half_rn(x[((size_t)b * TT + t) * FF + f]);
        return;
    }
    idx -= NCONV;
    if (idx < 3 * (size_t)G4) {
        int sel = (int)(idx >> 12), np = (int)(idx & 4095);
        int u = np >> 2, gate = np & 3;
        const float* b = (sel == 0) ? bl : (sel == 1) ? bc : br;
        float* dst = (sel == 0) ? g_benc : (sel == 1) ? g_bcell : g_brnn;
        dst[np] = b[gate * UU + u];
    }
}

// ------------------------- GEMM core (per-group) -----------------------------
// Warp tile 32m x 32n: acc[2 mt][4 nt][4]. Swizzled offsets factored:
//   offA(kk,mt) = offAb[mt] ^ (kk<<5)
//   offB(kk,nt) = offBb + kk*2048, then ^ (nt<<4)
__device__ __forceinline__ void mma_chunk(uint32_t bufA, uint32_t bufB,
                                          const uint32_t* offAb, uint32_t offBb,
                                          float acc[2][4][4]) {
#pragma unroll
    for (int kk = 0; kk < 4; kk++) {
        uint32_t af[2][4], bfr[4][2];
#pragma unroll
        for (int mt = 0; mt < 2; mt++)
            ldsm_x4(af[mt], bufA + (offAb[mt] ^ (kk << 5)));
        uint32_t bb = bufB + offBb + kk * 2048;
#pragma unroll
        for (int nt = 0; nt < 4; nt++)
            ldsm_x2t(bfr[nt], bb ^ (nt << 4));
#pragma unroll
        for (int mt = 0; mt < 2; mt++)
#pragma unroll
            for (int nt = 0; nt < 4; nt++)
                mma16816(acc[mt][nt], af[mt], bfr[nt]);
    }
}

// One group's GEMM over chunks [cg0, cg0+nchg). A = [A0 (k0g cols) | A1 (UU-stride)].
// B resident (gB==null): chunk c at su + c*8192. Else streamed into sW-region ring.
__device__ __forceinline__ void run_gemm(
    uint32_t su, int g, int lr, uint32_t colh, uint32_t obase,
    int cg0, int nchg,
    const __half* A0, int lda0, int k0g, const __half* A1,
    const __half* gB, int nbase, int mbase,
    const uint32_t* offAb, uint32_t offBb, float acc[2][4][4],
    int pre)
{
    auto issue = [&](int c) {
        int s = (c - cg0) % 3;
        uint32_t bufA = su + SA_OFF + (uint32_t)(g * 3 + s) * 8192;
        int kb = c << 6;
        const __half* srcA = (kb < k0g)
            ? A0 + (size_t)(mbase + lr) * lda0 + kb + colh
            : A1 + (size_t)(mbase + lr) * UU + (kb - k0g) + colh;
#pragma unroll
        for (int i = 0; i < 4; i++)
            cp16u(bufA + (obase ^ (i << 4)), srcA + i * 8);
        if (gB) {
            uint32_t bufB = su + (uint32_t)(g * 3 + s) * 8192;
            const __half* srcB = gB + (size_t)(kb + lr) * G4 + nbase + colh;
#pragma unroll
            for (int i = 0; i < 4; i++)
                cp16u(bufB + (obase ^ (i << 4)), srcB + i * 8);
        }
        cp_commit();
    };

    if (!pre) issue(cg0);
    issue(cg0 + 1);

    const int cend = cg0 + nchg;
    for (int c = cg0; c < cend; c++) {
        if (c < cend - 1) cp_wait<1>();
        else              cp_wait<0>();
        bar_named(1 + g);
        if (c + 2 < cend) issue(c + 2);
        int s = (c - cg0) % 3;
        uint32_t bufA = su + SA_OFF + (uint32_t)(g * 3 + s) * 8192;
        uint32_t bufB = gB ? (su + (uint32_t)(g * 3 + s) * 8192)
                           : (su + (uint32_t)c * 8192);
        mma_chunk(bufA, bufB, offAb, offBb, acc);
    }
}

// ------------------------- epilogue ------------------------------------------
__device__ __forceinline__ void epilogue(
    char* smem, float acc[2][4][4], const float* sBias, float* cst,
    __half* H16o, __half* H16o2, float* Hf,
    int g, int wm, int wn, int lane, int tid, int mbase, int ub)
{
    bar_named(1 + g);   // group's warps done reading its ring buffers
    float* sCg = (float*)(smem + SA_OFF + g * 24576);
    const int g2 = lane >> 2, t4 = lane & 3;
#pragma unroll
    for (int mt = 0; mt < 2; mt++)
#pragma unroll
        for (int nt = 0; nt < 4; nt++) {
            int r0 = wm * 32 + mt * 16 + g2;
            int c0 = wn * 32 + nt * 8 + 2 * t4;
            sCg[r0 * 68 + c0]           = acc[mt][nt][0];
            sCg[r0 * 68 + c0 + 1]       = acc[mt][nt][1];
            sCg[(r0 + 8) * 68 + c0]     = acc[mt][nt][2];
            sCg[(r0 + 8) * 68 + c0 + 1] = acc[mt][nt][3];
        }
    __syncthreads();
    const float* sC0 = (const float*)(smem + SA_OFF);
    const float* sC1 = (const float*)(smem + SA_OFF + 24576);
    const float* sC2 = (const float*)(smem + SA_OFF + 49152);
    const float4* b4 = (const float4*)sBias;
#pragma unroll
    for (int i = 0; i < 3; i++) {
        int p = tid + i * NT;
        if (p < 1024) {
            int bl = p >> 4, ul = p & 15;
            float4 z0 = *(const float4*)&sC0[bl * 68 + ul * 4];
            float4 z1 = *(const float4*)&sC1[bl * 68 + ul * 4];
            float4 z2 = *(const float4*)&sC2[bl * 68 + ul * 4];
            float4 bz = b4[ul];
            float zi = z0.x + z1.x + z2.x + bz.x;
            float zf = z0.y + z1.y + z2.y + bz.y;
            float zg = z0.z + z1.z + z2.z + bz.z;
            float zo = z0.w + z1.w + z2.w + bz.w;
            float cn = sigmoidf_fast(zf) * cst[i] + sigmoidf_fast(zi) * tanhf(zg);
            float h = sigmoidf_fast(zo) * tanhf(cn);
            cst[i] = cn;
            int idx = (mbase + bl) * UU + ub + ul;
            __half h16 = __float2half_rn(h);
            H16o[idx] = h16;
            if (H16o2) H16o2[idx] = h16;
            if (Hf) Hf[idx] = h;
        }
    }
    __syncthreads();    // gates done reading sC before rings are reused
}

// Dense head for batch row b. Threads 0-255 compute (8 per unit).
__device__ __forceinline__ void dense_cta(
    int b, int s, const float* hsrc,
    const float* __restrict__ W1, const float* __restrict__ b1,
    const float* __restrict__ W2, const float* __restrict__ b2,
    float* __restrict__ out, float* sRed, int tid)
{
    if (tid < 256) {
        int j = tid >> 3, l8 = tid & 7;
        float p = 0.0f;
        const float* hb = hsrc + (size_t)b * UU;
        for (int k = l8; k < UU; k += 8) p += __ldcg(&hb[k]) * W1[k * DH + j];
        p += __shfl_xor_sync(0xffffffffu, p, 1);
        p += __shfl_xor_sync(0xffffffffu, p, 2);
        p += __shfl_xor_sync(0xffffffffu, p, 4);
        if (l8 == 0) sRed[j] = fmaxf(p + b1[j], 0.0f);
    }
    __syncthreads();
    if (tid < FF) {
        float a = b2[tid];
#pragma unroll
        for (int jj = 0; jj < DH; jj++) a += sRed[jj] * W2[jj * FF + tid];
        out[((size_t)b * OUTS + s) * FF + tid] = a;
        g_P16[b * FF + tid] = __float2half_rn(a);
    }
    __syncthreads();
}

__device__ __forceinline__ void zero_acc(float acc[2][4][4]) {
#pragma unroll
    for (int i = 0; i < 2; i++)
#pragma unroll
        for (int j = 0; j < 4; j++)
#pragma unroll
            for (int q = 0; q < 4; q++) acc[i][j][q] = 0.0f;
}

// ------------------------- THE persistent kernel ----------------------------
__global__ void __launch_bounds__(NT, 1) rnn_all(
    const float* __restrict__ W1, const float* __restrict__ b1,
    const float* __restrict__ W2, const float* __restrict__ b2,
    float* __restrict__ out)
{
    extern __shared__ char smem[];
    uint32_t su;
    asm("{ .reg .u64 t; cvta.to.shared.u64 t, %1; cvt.u32.u64 %0, t; }"
        : "=r"(su) : "l"(smem));
    __shared__ float sBias[192];
    __shared__ float sRed[DH];

    const int tid = threadIdx.x, lane = tid & 31, warp = tid >> 5;
    const int g = warp >> 2;                 // k-split group 0/1/2
    const int wg = warp & 3, wm = wg >> 1, wn = wg & 1;
    const int cta = blockIdx.x;
    const int mbase = (cta & 1) * 64, nbase = (cta >> 1) * 64;
    const int ub = nbase >> 2;
    const int tg = tid & 127;                // thread id within group
    const int lr = tg >> 1;                  // load row 0..63
    const uint32_t colh = (tg & 1) * 32;     // load col (halves)
    const uint32_t obase = SWZ((uint32_t)(lr * 128) + colh * 2);

    // factored swizzled ldsm offsets
    uint32_t offAb[2], offBb;
    {
        const int lrow = lane & 7, lsel = lane >> 3;
#pragma unroll
        for (int mt = 0; mt < 2; mt++) {
            int row = wm * 32 + mt * 16 + lrow + ((lsel & 1) << 3);
            offAb[mt] = SWZ((uint32_t)(row * 128 + ((lsel >> 1) << 4)));
        }
        offBb = SWZ((uint32_t)((lane & 15) * 128 + wn * 64));
    }

    unsigned long long bar_base = 0ull;
    int bar_cnt = 0;

    if (tid < 64) {
        sBias[tid]       = g_benc[nbase + tid];
        sBias[64 + tid]  = g_bcell[nbase + tid];
        sBias[128 + tid] = g_brnn[nbase + tid];
    }
    // zero h0 slice
    if (tid < 128) {
        uint4 z = {0, 0, 0, 0};
        ((uint4*)g_H16[0])[cta * 128 + tid] = z;
    }
    // resident encoder weights: 17 chunks x 64 rows x 8 x 16B
    for (int i = tid; i < 17 * 512; i += NT) {
        int c = i >> 9, r = (i >> 3) & 63, u = i & 7;
        cp16u(su + (uint32_t)c * 8192 + SWZ((uint32_t)(r * 128 + u * 16)),
              g_Wenc + (size_t)(c * 64 + r) * G4 + nbase + u * 8);
    }
    cp_commit();
    cp_wait<0>();
    __syncthreads();

    // pre-issue x_0 chunk (group 0, stage 0)
    if (g == 0) {
        const __half* src = g_XF16 + (size_t)(mbase + lr) * FF + colh;
#pragma unroll
        for (int i = 0; i < 4; i++)
            cp16u(su + SA_OFF + (obase ^ (i << 4)), src + i * 8);
        cp_commit();
    }

    float cl[3] = {0, 0, 0}, cr[3];
    grid_barrier(bar_base, bar_cnt);

    float acc[2][4][4];
    const int cg0e = (g == 0) ? 0 : (g == 1) ? 6 : 12;   // 17 -> 6/6/5
    const int nchge = (g == 2) ? 5 : 6;
    const int cg0r = g * 11;                             // 32 -> 11/11/10
    const int nchgr = (g == 2) ? 10 : 11;

    // ---------------- encoder: 256 steps ----------------
#pragma unroll 1
    for (int t = 0; t < TT; t++) {
        zero_acc(acc);
        run_gemm(su, g, lr, colh, obase, cg0e, nchge,
                 g_XF16 + (size_t)t * BB * FF, FF, FF, g_H16[t & 1],
                 nullptr, nbase, mbase, offAb, offBb, acc, (g == 0) ? 1 : 0);
        bool last = (t == TT - 1);
        epilogue(smem, acc, sBias, cl,
                 g_H16[(t + 1) & 1],
                 last ? g_HR16[0] : nullptr,
                 last ? g_Hl : nullptr,
                 g, wm, wn, lane, tid, mbase, ub);
        if (!last && g == 0) {
            const __half* src = g_XF16 + (size_t)(t + 1) * BB * FF
                              + (size_t)(mbase + lr) * FF + colh;
#pragma unroll
            for (int i = 0; i < 4; i++)
                cp16u(su + SA_OFF + (obase ^ (i << 4)), src + i * 8);
            cp_commit();
        }
        grid_barrier(bar_base, bar_cnt);
    }
    cr[0] = cl[0]; cr[1] = cl[1]; cr[2] = cl[2];

    // pred0 = dense(encoder h)
    dense_cta(cta, 0, g_Hl, W1, b1, W2, b2, out, sRed, tid);
    grid_barrier(bar_base, bar_cnt);

    // ---------------- decoder: 31 steps (weights streamed via sW-region rings)
#pragma unroll 1
    for (int s = 1; s < OUTS; s++) {
        // lstm_cell: A = [pred | hl], B = Wcell streamed
        zero_acc(acc);
        run_gemm(su, g, lr, colh, obase, cg0e, nchge,
                 g_P16, FF, FF, g_H16[(s + 1) & 1],
                 g_Wcell, nbase, mbase, offAb, offBb, acc, 0);
        epilogue(smem, acc, sBias + 64, cl,
                 g_H16[s & 1], nullptr, nullptr,
                 g, wm, wn, lane, tid, mbase, ub);
        grid_barrier(bar_base, bar_cnt);

        // rnn_cell: A = [hl | hr], B = Wrnn streamed
        zero_acc(acc);
        run_gemm(su, g, lr, colh, obase, cg0r, nchgr,
                 g_H16[s & 1], UU, UU, g_HR16[(s + 1) & 1],
                 g_Wrnn, nbase, mbase, offAb, offBb, acc, 0);
        epilogue(smem, acc, sBias + 128, cr,
                 g_HR16[s & 1], nullptr, g_Hr,
                 g, wm, wn, lane, tid, mbase, ub);
        grid_barrier(bar_base, bar_cnt);

        dense_cta(cta, s, g_Hr, W1, b1, W2, b2, out, sRed, tid);
        grid_barrier(bar_base, bar_cnt);
    }
}

// ------------------------- launcher -----------------------------------------
extern "C" void kernel_launch(void* const* d_in, const int* in_sizes, int n_in,
                              void* d_out, int out_size) {
    const float* inputs = (const float*)d_in[0];
    const float* Wl = (const float*)d_in[1];
    const float* Rl = (const float*)d_in[2];
    const float* bl = (const float*)d_in[3];
    const float* Wc = (const float*)d_in[4];
    const float* Rc = (const float*)d_in[5];
    const float* bc = (const float*)d_in[6];
    const float* Wr = (const float*)d_in[7];
    const float* Rr = (const float*)d_in[8];
    const float* br = (const float*)d_in[9];
    const float* W1 = (const float*)d_in[10];
    const float* b1 = (const float*)d_in[11];
    const float* W2 = (const float*)d_in[12];
    const float* b2 = (const float*)d_in[13];
    float* out = (float*)d_out;

    cudaFuncSetAttribute(rnn_all, cudaFuncAttributeMaxDynamicSharedMemorySize,
                         DYN_BYTES);

    size_t total = 2 * (size_t)KENC * G4 + (size_t)KRNN * G4
                 + (size_t)TT * BB * FF + 3 * (size_t)G4;
    prep_all<<<(int)((total + 255) / 256), 256>>>(Wl, Rl, bl, Wc, Rc, bc,
                                                  Wr, Rr, br, inputs);

    rnn_all<<<NB, NT, DYN_BYTES>>>(W1, b1, W2, b2, out);
}

// round 16
// speedup vs baseline: 1.4167x; 1.4167x over previous
#include <cuda_runtime.h>
#include <cuda_fp16.h>
#include <cstdint>

// Problem dims
#define BB   128
#define TT   256
#define FF   64
#define UU   1024
#define G4   4096
#define OUTS 32
#define DH   32
#define KENC 1088      // F + U -> 17 chunks of K=64
#define KRNN 2048      // U + U -> 32 chunks
#define NB   128       // persistent grid size
#define NBH  64        // CTAs per barrier domain (independent batch halves)
#define NT   512       // threads: 4 groups x 4 warps

// Dynamic smem layout (bytes), all tiles 64 rows x 128B, XOR-swizzled
#define SW_OFF 0                         // 17 x 8192 resident W / decoder B rings
#define SA_OFF (17 * 8192)               // 139264: 11 x 8192 A ring bufs
#define DYN_BYTES (SA_OFF + 11 * 8192)   // 229376

#define SWZ(o) ((o) ^ (((o) >> 3) & 0x70))

// ------------------------- device scratch -----------------------------------
__device__ __align__(16) __half g_XF16[(size_t)TT * BB * FF];  // [t][b][f]
__device__ __align__(16) __half g_Wenc[(size_t)KENC * G4];     // [k][n'], n'=u*4+gate
__device__ __align__(16) __half g_Wcell[(size_t)KENC * G4];
__device__ __align__(16) __half g_Wrnn[(size_t)KRNN * G4];
__device__ float g_benc[G4], g_bcell[G4], g_brnn[G4];
__device__ float g_Hl[BB * UU], g_Hr[BB * UU];
__device__ __align__(16) __half g_H16[2][BB * UU];
__device__ __align__(16) __half g_HR16[2][BB * UU];
__device__ __align__(16) __half g_P16[BB * FF];
__device__ unsigned long long g_tick2[32];   // [0]: half 0, [16]: half 1

// ------------------------- PTX helpers --------------------------------------
__device__ __forceinline__ void cp16u(uint32_t s, const void* g) {
    asm volatile("cp.async.cg.shared.global [%0], [%1], 16;" :: "r"(s), "l"(g));
}
__device__ __forceinline__ void cp_commit() { asm volatile("cp.async.commit_group;"); }
template<int N> __device__ __forceinline__ void cp_wait() {
    asm volatile("cp.async.wait_group %0;" :: "n"(N));
}
__device__ __forceinline__ void bar_named(int id) {
    asm volatile("bar.sync %0, 128;" :: "r"(id) : "memory");
}
__device__ __forceinline__ void ldsm_x4(uint32_t* r, uint32_t a) {
    asm volatile("ldmatrix.sync.aligned.m8n8.x4.shared.b16 {%0,%1,%2,%3}, [%4];"
                 : "=r"(r[0]), "=r"(r[1]), "=r"(r[2]), "=r"(r[3]) : "r"(a));
}
__device__ __forceinline__ void ldsm_x2t(uint32_t* r, uint32_t a) {
    asm volatile("ldmatrix.sync.aligned.m8n8.x2.trans.shared.b16 {%0,%1}, [%2];"
                 : "=r"(r[0]), "=r"(r[1]) : "r"(a));
}
__device__ __forceinline__ void mma16816(float* c, const uint32_t* a, const uint32_t* b) {
    asm volatile(
        "mma.sync.aligned.m16n8k16.row.col.f32.f16.f16.f32 "
        "{%0,%1,%2,%3}, {%4,%5,%6,%7}, {%8,%9}, {%0,%1,%2,%3};"
        : "+f"(c[0]), "+f"(c[1]), "+f"(c[2]), "+f"(c[3])
        : "r"(a[0]), "r"(a[1]), "r"(a[2]), "r"(a[3]), "r"(b[0]), "r"(b[1]));
}
__device__ __forceinline__ float sigmoidf_fast(float x) {
    return 1.0f / (1.0f + __expf(-x));
}

// Grid barrier over one 64-CTA domain: monotone ticket (replay-safe).
__device__ __forceinline__ void grid_barrier(unsigned long long* tick,
                                             unsigned long long& base, int& cnt) {
    __threadfence();
    __syncthreads();
    if (threadIdx.x == 0) {
        if (cnt == 0) {
            unsigned long long v = atomicAdd(tick, 1ull);
            base = (v / NBH) * NBH;
        } else {
            atomicAdd(tick, 1ull);   // fire-and-forget
        }
        cnt++;
        unsigned long long target = base + (unsigned long long)cnt * NBH;
        while (*(volatile unsigned long long*)tick < target) __nanosleep(16);
        __threadfence();
    }
    __syncthreads();
}

// ------------------------- merged prep kernel --------------------------------
__global__ void prep_all(
    const float* __restrict__ Wl, const float* __restrict__ Rl, const float* __restrict__ bl,
    const float* __restrict__ Wc, const float* __restrict__ Rc, const float* __restrict__ bc,
    const float* __restrict__ Wr, const float* __restrict__ Rr, const float* __restrict__ br,
    const float* __restrict__ x)
{
    size_t idx = (size_t)blockIdx.x * 256 + threadIdx.x;
    const size_t NENC  = (size_t)KENC * G4;
    const size_t NRNN  = (size_t)KRNN * G4;
    const size_t NCONV = (size_t)TT * BB * FF;

    if (idx < NENC) {
        size_t k = idx >> 12; int np = (int)(idx & 4095);
        int u = np >> 2, gate = np & 3, col = gate * UU + u;
        float v = (k < FF) ? Wl[k * G4 + col] : Rl[(k - FF) * G4 + col];
        g_Wenc[idx] = __float2half_rn(v);
        return;
    }
    idx -= NENC;
    if (idx < NENC) {
        size_t k = idx >> 12; int np = (int)(idx & 4095);
        int u = np >> 2, gate = np & 3, col = gate * UU + u;
        float v = (k < FF) ? Wc[k * G4 + col] : Rc[(k - FF) * G4 + col];
        g_Wcell[idx] = __float2half_rn(v);
        return;
    }
    idx -= NENC;
    if (idx < NRNN) {
        size_t k = idx >> 12; int np = (int)(idx & 4095);
        int u = np >> 2, gate = np & 3, col = gate * UU + u;
        float v = (k < UU) ? Wr[k * G4 + col] : Rr[(k - UU) * G4 + col];
        g_Wrnn[idx] = __float2half_rn(v);
        return;
    }
    idx -= NRNN;
    if (idx < NCONV) {
        size_t t = idx / (BB * FF);
        int r = (int)(idx % (BB * FF));
        int b = r / FF, f = r % FF;
        g_XF16[idx] = __float2half_rn(x[((size_t)b * TT + t) * FF + f]);
        return;
    }
    idx -= NCONV;
    if (idx < 3 * (size_t)G4) {
        int sel = (int)(idx >> 12), np = (int)(idx & 4095);
        int u = np >> 2, gate = np & 3;
        const float* b = (sel == 0) ? bl : (sel == 1) ? bc : br;
        float* dst = (sel == 0) ? g_benc : (sel == 1) ? g_bcell : g_brnn;
        dst[np] = b[gate * UU + u];
    }
}

// ------------------------- GEMM core (per-group) -----------------------------
// Warp tile 32m x 32n: acc[2 mt][4 nt][4].
//   offA(kk,mt) = offAb[mt] ^ (kk<<5)
//   offB(kk,nt) = offBb + kk*2048, then ^ (nt<<4)
__device__ __forceinline__ void mma_chunk(uint32_t bufA, uint32_t bufB,
                                          const uint32_t* offAb, uint32_t offBb,
                                          float acc[2][4][4]) {
#pragma unroll
    for (int kk = 0; kk < 4; kk++) {
        uint32_t af[2][4], bfr[4][2];
#pragma unroll
        for (int mt = 0; mt < 2; mt++)
            ldsm_x4(af[mt], bufA + (offAb[mt] ^ (kk << 5)));
        uint32_t bb = bufB + offBb + kk * 2048;
#pragma unroll
        for (int nt = 0; nt < 4; nt++)
            ldsm_x2t(bfr[nt], bb ^ (nt << 4));
#pragma unroll
        for (int mt = 0; mt < 2; mt++)
#pragma unroll
            for (int nt = 0; nt < 4; nt++)
                mma16816(acc[mt][nt], af[mt], bfr[nt]);
    }
}

// One group's GEMM over chunks [cg0, cg0+nchg). A = [A0 (k0g cols) | A1 (UU-stride)].
// B resident (gB==null): chunk c at su + c*8192. Else streamed into SW-area ring.
// Ring: depth bufs starting at buf index bufb (A at SA_OFF, B at SW area).
__device__ __forceinline__ void run_gemm(
    uint32_t su, int g, int bufb, int depth, int lr, uint32_t colh, uint32_t obase,
    int cg0, int nchg,
    const __half* A0, int lda0, int k0g, const __half* A1,
    const __half* gB, int nbase, int mbase,
    const uint32_t* offAb, uint32_t offBb, float acc[2][4][4],
    int pre)
{
    auto issue = [&](int c) {
        int s = (c - cg0) % depth;
        uint32_t bufA = su + SA_OFF + (uint32_t)(bufb + s) * 8192;
        int kb = c << 6;
        const __half* srcA = (kb < k0g)
            ? A0 + (size_t)(mbase + lr) * lda0 + kb + colh
            : A1 + (size_t)(mbase + lr) * UU + (kb - k0g) + colh;
#pragma unroll
        for (int i = 0; i < 4; i++)
            cp16u(bufA + (obase ^ (i << 4)), srcA + i * 8);
        if (gB) {
            uint32_t bufB = su + (uint32_t)(bufb + s) * 8192;
            const __half* srcB = gB + (size_t)(kb + lr) * G4 + nbase + colh;
#pragma unroll
            for (int i = 0; i < 4; i++)
                cp16u(bufB + (obase ^ (i << 4)), srcB + i * 8);
        }
        cp_commit();
    };

    if (!pre) issue(cg0);
    if (depth == 3) issue(cg0 + 1);

    const int cend = cg0 + nchg;
    for (int c = cg0; c < cend; c++) {
        if (depth == 3 && c < cend - 1) cp_wait<1>();
        else                            cp_wait<0>();
        bar_named(1 + g);
        if (c + depth - 1 < cend) issue(c + depth - 1);
        int s = (c - cg0) % depth;
        uint32_t bufA = su + SA_OFF + (uint32_t)(bufb + s) * 8192;
        uint32_t bufB = gB ? (su + (uint32_t)(bufb + s) * 8192)
                           : (su + (uint32_t)c * 8192);
        mma_chunk(bufA, bufB, offAb, offBb, acc);
    }
}

// ------------------------- epilogue ------------------------------------------
// sC partials: stride 64 floats, region g at SA_OFF + bufb[g]*8192 (16384 B).
__device__ __forceinline__ void epilogue(
    char* smem, float acc[2][4][4], const float* sBias, float* cst,
    __half* H16o, __half* H16o2, float* Hf,
    int g, int bufb, int wm, int wn, int lane, int tid, int mbase, int ub)
{
    bar_named(1 + g);   // group's warps done reading its ring buffers
    float* sCg = (float*)(smem + SA_OFF + bufb * 8192);
    const int g2 = lane >> 2, t4 = lane & 3;
#pragma unroll
    for (int mt = 0; mt < 2; mt++)
#pragma unroll
        for (int nt = 0; nt < 4; nt++) {
            int r0 = wm * 32 + mt * 16 + g2;
            int c0 = wn * 32 + nt * 8 + 2 * t4;
            sCg[r0 * 64 + c0]           = acc[mt][nt][0];
            sCg[r0 * 64 + c0 + 1]       = acc[mt][nt][1];
            sCg[(r0 + 8) * 64 + c0]     = acc[mt][nt][2];
            sCg[(r0 + 8) * 64 + c0 + 1] = acc[mt][nt][3];
        }
    __syncthreads();
    const float* sC0 = (const float*)(smem + SA_OFF);
    const float* sC1 = (const float*)(smem + SA_OFF + 3 * 8192);
    const float* sC2 = (const float*)(smem + SA_OFF + 6 * 8192);
    const float* sC3 = (const float*)(smem + SA_OFF + 9 * 8192);
    const float4* b4 = (const float4*)sBias;
#pragma unroll
    for (int i = 0; i < 2; i++) {
        int p = tid + i * NT;
        int bl = p >> 4, ul = p & 15;
        float4 z0 = *(const float4*)&sC0[bl * 64 + ul * 4];
        float4 z1 = *(const float4*)&sC1[bl * 64 + ul * 4];
        float4 z2 = *(const float4*)&sC2[bl * 64 + ul * 4];
        float4 z3 = *(const float4*)&sC3[bl * 64 + ul * 4];
        float4 bz = b4[ul];
        float zi = z0.x + z1.x + z2.x + z3.x + bz.x;
        float zf = z0.y + z1.y + z2.y + z3.y + bz.y;
        float zg = z0.z + z1.z + z2.z + z3.z + bz.z;
        float zo = z0.w + z1.w + z2.w + z3.w + bz.w;
        float cn = sigmoidf_fast(zf) * cst[i] + sigmoidf_fast(zi) * tanhf(zg);
        float h = sigmoidf_fast(zo) * tanhf(cn);
        cst[i] = cn;
        int idx = (mbase + bl) * UU + ub + ul;
        __half h16 = __float2half_rn(h);
        H16o[idx] = h16;
        if (H16o2) H16o2[idx] = h16;
        if (Hf) Hf[idx] = h;
    }
    __syncthreads();    // gates done reading sC before rings are reused
}

// Dense head for batch row b (512 threads, 16 per unit).
__device__ __forceinline__ void dense_cta(
    int b, int s, const float* hsrc,
    const float* __restrict__ W1, const float* __restrict__ b1,
    const float* __restrict__ W2, const float* __restrict__ b2,
    float* __restrict__ out, float* sRed, int tid)
{
    int j = tid >> 4, l16 = tid & 15;
    float p = 0.0f;
    const float* hb = hsrc + (size_t)b * UU;
    for (int k = l16; k < UU; k += 16) p += __ldcg(&hb[k]) * W1[k * DH + j];
    p += __shfl_xor_sync(0xffffffffu, p, 1);
    p += __shfl_xor_sync(0xffffffffu, p, 2);
    p += __shfl_xor_sync(0xffffffffu, p, 4);
    p += __shfl_xor_sync(0xffffffffu, p, 8);
    if (l16 == 0) sRed[j] = fmaxf(p + b1[j], 0.0f);
    __syncthreads();
    if (tid < FF) {
        float a = b2[tid];
#pragma unroll
        for (int jj = 0; jj < DH; jj++) a += sRed[jj] * W2[jj * FF + tid];
        out[((size_t)b * OUTS + s) * FF + tid] = a;
        g_P16[b * FF + tid] = __float2half_rn(a);
    }
    __syncthreads();
}

__device__ __forceinline__ void zero_acc(float acc[2][4][4]) {
#pragma unroll
    for (int i = 0; i < 2; i++)
#pragma unroll
        for (int j = 0; j < 4; j++)
#pragma unroll
            for (int q = 0; q < 4; q++) acc[i][j][q] = 0.0f;
}

// ------------------------- THE persistent kernel ----------------------------
__global__ void __launch_bounds__(NT, 1) rnn_all(
    const float* __restrict__ W1, const float* __restrict__ b1,
    const float* __restrict__ W2, const float* __restrict__ b2,
    float* __restrict__ out)
{
    extern __shared__ char smem[];
    uint32_t su;
    asm("{ .reg .u64 t; cvta.to.shared.u64 t, %1; cvt.u32.u64 %0, t; }"
        : "=r"(su) : "l"(smem));
    __shared__ float sBias[192];
    __shared__ float sRed[DH];

    const int tid = threadIdx.x, lane = tid & 31, warp = tid >> 5;
    const int g = warp >> 2;                 // k-split group 0..3
    const int wg = warp & 3, wm = wg >> 1, wn = wg & 1;
    const int cta = blockIdx.x;
    const int mbase = (cta & 1) * 64, nbase = (cta >> 1) * 64;
    const int ub = nbase >> 2;
    const int bden = ((cta & 1) << 6) | (cta >> 1);   // dense batch row (own half)
    unsigned long long* tick = &g_tick2[(cta & 1) * 16];
    const int tg = tid & 127;                // thread id within group
    const int lr = tg >> 1;                  // load row 0..63
    const uint32_t colh = (tg & 1) * 32;     // load col (halves)
    const uint32_t obase = SWZ((uint32_t)(lr * 128) + colh * 2);

    // group ring base + depth: {3,3,3,2} bufs at {0,3,6,9}
    const int bufb = g * 3;
    const int depth = (g == 3) ? 2 : 3;

    // factored swizzled ldsm offsets
    uint32_t offAb[2], offBb;
    {
        const int lrow = lane & 7, lsel = lane >> 3;
#pragma unroll
        for (int mt = 0; mt < 2; mt++) {
            int row = wm * 32 + mt * 16 + lrow + ((lsel & 1) << 3);
            offAb[mt] = SWZ((uint32_t)(row * 128 + ((lsel >> 1) << 4)));
        }
        offBb = SWZ((uint32_t)((lane & 15) * 128 + wn * 64));
    }

    unsigned long long bar_base = 0ull;
    int bar_cnt = 0;

    if (tid < 64) {
        sBias[tid]       = g_benc[nbase + tid];
        sBias[64 + tid]  = g_bcell[nbase + tid];
        sBias[128 + tid] = g_brnn[nbase + tid];
    }
    // zero h0 slice
    if (tid < 128) {
        uint4 z = {0, 0, 0, 0};
        ((uint4*)g_H16[0])[cta * 128 + tid] = z;
    }
    // resident encoder weights: 17 chunks x 64 rows x 8 x 16B
    for (int i = tid; i < 17 * 512; i += NT) {
        int c = i >> 9, r = (i >> 3) & 63, u = i & 7;
        cp16u(su + (uint32_t)c * 8192 + SWZ((uint32_t)(r * 128 + u * 16)),
              g_Wenc + (size_t)(c * 64 + r) * G4 + nbase + u * 8);
    }
    cp_commit();
    cp_wait<0>();
    __syncthreads();

    // pre-issue x_0 chunk (group 0, stage 0)
    if (g == 0) {
        const __half* src = g_XF16 + (size_t)(mbase + lr) * FF + colh;
#pragma unroll
        for (int i = 0; i < 4; i++)
            cp16u(su + SA_OFF + (obase ^ (i << 4)), src + i * 8);
        cp_commit();
    }

    float cl[2] = {0, 0}, cr[2];
    grid_barrier(tick, bar_base, bar_cnt);

    float acc[2][4][4];
    // encoder/lstm chunk split 17 -> 5/4/4/4 ; rnn 32 -> 8/8/8/8
    const int cg0e = (g == 0) ? 0 : (1 + g * 4);
    const int nchge = (g == 0) ? 5 : 4;
    const int cg0r = g * 8;

    // ---------------- encoder: 256 steps ----------------
#pragma unroll 1
    for (int t = 0; t < TT; t++) {
        zero_acc(acc);
        run_gemm(su, g, bufb, depth, lr, colh, obase, cg0e, nchge,
                 g_XF16 + (size_t)t * BB * FF, FF, FF, g_H16[t & 1],
                 nullptr, nbase, mbase, offAb, offBb, acc, (g == 0) ? 1 : 0);
        bool last = (t == TT - 1);
        epilogue(smem, acc, sBias, cl,
                 g_H16[(t + 1) & 1],
                 last ? g_HR16[0] : nullptr,
                 last ? g_Hl : nullptr,
                 g, bufb, wm, wn, lane, tid, mbase, ub);
        if (!last && g == 0) {
            const __half* src = g_XF16 + (size_t)(t + 1) * BB * FF
                              + (size_t)(mbase + lr) * FF + colh;
#pragma unroll
            for (int i = 0; i < 4; i++)
                cp16u(su + SA_OFF + (obase ^ (i << 4)), src + i * 8);
            cp_commit();
        }
        grid_barrier(tick, bar_base, bar_cnt);
    }
    cr[0] = cl[0]; cr[1] = cl[1];

    // pred0 = dense(encoder h)
    dense_cta(bden, 0, g_Hl, W1, b1, W2, b2, out, sRed, tid);
    grid_barrier(tick, bar_base, bar_cnt);

    // ---------------- decoder: 31 steps (weights streamed via SW-area rings)
#pragma unroll 1
    for (int s = 1; s < OUTS; s++) {
        // lstm_cell: A = [pred | hl], B = Wcell streamed
        zero_acc(acc);
        run_gemm(su, g, bufb, depth, lr, colh, obase, cg0e, nchge,
                 g_P16, FF, FF, g_H16[(s + 1) & 1],
                 g_Wcell, nbase, mbase, offAb, offBb, acc, 0);
        epilogue(smem, acc, sBias + 64, cl,
                 g_H16[s & 1], nullptr, nullptr,
                 g, bufb, wm, wn, lane, tid, mbase, ub);
        grid_barrier(tick, bar_base, bar_cnt);

        // rnn_cell: A = [hl | hr], B = Wrnn streamed
        zero_acc(acc);
        run_gemm(su, g, bufb, depth, lr, colh, obase, cg0r, 8,
                 g_H16[s & 1], UU, UU, g_HR16[(s + 1) & 1],
                 g_Wrnn, nbase, mbase, offAb, offBb, acc, 0);
        epilogue(smem, acc, sBias + 128, cr,
                 g_HR16[s & 1], nullptr, g_Hr,
                 g, bufb, wm, wn, lane, tid, mbase, ub);
        grid_barrier(tick, bar_base, bar_cnt);

        dense_cta(bden, s, g_Hr, W1, b1, W2, b2, out, sRed, tid);
        grid_barrier(tick, bar_base, bar_cnt);
    }
}

// ------------------------- launcher -----------------------------------------
extern "C" void kernel_launch(void* const* d_in, const int* in_sizes, int n_in,
                              void* d_out, int out_size) {
    const float* inputs = (const float*)d_in[0];
    const float* Wl = (const float*)d_in[1];
    const float* Rl = (const float*)d_in[2];
    const float* bl = (const float*)d_in[3];
    const float* Wc = (const float*)d_in[4];
    const float* Rc = (const float*)d_in[5];
    const float* bc = (const float*)d_in[6];
    const float* Wr = (const float*)d_in[7];
    const float* Rr = (const float*)d_in[8];
    const float* br = (const float*)d_in[9];
    const float* W1 = (const float*)d_in[10];
    const float* b1 = (const float*)d_in[11];
    const float* W2 = (const float*)d_in[12];
    const float* b2 = (const float*)d_in[13];
    float* out = (float*)d_out;

    cudaFuncSetAttribute(rnn_all, cudaFuncAttributeMaxDynamicSharedMemorySize,
                         DYN_BYTES);

    size_t total = 2 * (size_t)KENC * G4 + (size_t)KRNN * G4
                 + (size_t)TT * BB * FF + 3 * (size_t)G4;
    prep_all<<<(int)((total + 255) / 256), 256>>>(Wl, Rl, bl, Wc, Rc, bc,
                                                  Wr, Rr, br, inputs);

    rnn_all<<<NB, NT, DYN_BYTES>>>(W1, b1, W2, b2, out);
}

// round 17
// speedup vs baseline: 1.6802x; 1.1860x over previous
#include <cuda_runtime.h>
#include <cuda_fp16.h>
#include <cstdint>

// Problem dims
#define BB   128
#define TT   256
#define FF   64
#define UU   1024
#define G4   4096
#define OUTS 32
#define DH   32
#define KENC 1088      // F + U -> 17 chunks of K=64
#define KRNN 2048      // U + U -> 32 chunks
#define NB   128       // persistent grid size
#define NBH  64        // CTAs per barrier domain (independent batch halves)
#define NT   512       // threads: 2 groups x 8 warps

// Dynamic smem layout (bytes), all tiles 64 rows x 128B, XOR-swizzled
#define SW_OFF 0                        // 17 x 8192 resident W / decoder B rings
#define SA_OFF (17 * 8192)              // 139264: 6 x 8192 A rings (3 per group)
#define DYN_BYTES (SA_OFF + 6 * 8192)   // 188416

#define SWZ(o) ((o) ^ (((o) >> 3) & 0x70))

// ------------------------- device scratch -----------------------------------
__device__ __align__(16) __half g_XF16[(size_t)TT * BB * FF];  // [t][b][f]
__device__ __align__(16) __half g_Wenc[(size_t)KENC * G4];     // [k][n'], n'=u*4+gate
__device__ __align__(16) __half g_Wcell[(size_t)KENC * G4];
__device__ __align__(16) __half g_Wrnn[(size_t)KRNN * G4];
__device__ float g_benc[G4], g_bcell[G4], g_brnn[G4];
__device__ float g_Hl[BB * UU], g_Hr[BB * UU];
__device__ __align__(16) __half g_H16[2][BB * UU];
__device__ __align__(16) __half g_HR16[2][BB * UU];
__device__ __align__(16) __half g_P16[BB * FF];
__device__ unsigned long long g_tick2[32];   // [0]: half 0, [16]: half 1

// ------------------------- PTX helpers --------------------------------------
__device__ __forceinline__ void cp16u(uint32_t s, const void* g) {
    asm volatile("cp.async.cg.shared.global [%0], [%1], 16;" :: "r"(s), "l"(g));
}
__device__ __forceinline__ void cp_commit() { asm volatile("cp.async.commit_group;"); }
template<int N> __device__ __forceinline__ void cp_wait() {
    asm volatile("cp.async.wait_group %0;" :: "n"(N));
}
__device__ __forceinline__ void bar_named(int id) {
    asm volatile("bar.sync %0, 256;" :: "r"(id) : "memory");
}
__device__ __forceinline__ void ldsm_x4(uint32_t* r, uint32_t a) {
    asm volatile("ldmatrix.sync.aligned.m8n8.x4.shared.b16 {%0,%1,%2,%3}, [%4];"
                 : "=r"(r[0]), "=r"(r[1]), "=r"(r[2]), "=r"(r[3]) : "r"(a));
}
__device__ __forceinline__ void ldsm_x2t(uint32_t* r, uint32_t a) {
    asm volatile("ldmatrix.sync.aligned.m8n8.x2.trans.shared.b16 {%0,%1}, [%2];"
                 : "=r"(r[0]), "=r"(r[1]) : "r"(a));
}
__device__ __forceinline__ void mma16816(float* c, const uint32_t* a, const uint32_t* b) {
    asm volatile(
        "mma.sync.aligned.m16n8k16.row.col.f32.f16.f16.f32 "
        "{%0,%1,%2,%3}, {%4,%5,%6,%7}, {%8,%9}, {%0,%1,%2,%3};"
        : "+f"(c[0]), "+f"(c[1]), "+f"(c[2]), "+f"(c[3])
        : "r"(a[0]), "r"(a[1]), "r"(a[2]), "r"(a[3]), "r"(b[0]), "r"(b[1]));
}

// ---------------- FMA/ALU-only activations (no MUFU, no F2I/FRND) -----------
// exp(x) for |x| <= 85: magic-constant round + deg-5 exp2 poly + exponent insert.
__device__ __forceinline__ float fast_exp(float x) {
    float t = fmaf(x, 1.442695041f, 12582912.0f);   // RN to integer in low mantissa
    int   k = __float_as_int(t);                    // low bits hold round(x*log2e)
    float kf = t - 12582912.0f;
    float f = fmaf(x, 1.442695041f, -kf);           // f in [-0.5, 0.5]
    float p = 1.8775767e-3f;
    p = fmaf(p, f, 8.9893397e-3f);
    p = fmaf(p, f, 5.5826318e-2f);
    p = fmaf(p, f, 2.4015361e-1f);
    p = fmaf(p, f, 6.9315308e-1f);
    p = fmaf(p, f, 1.0f);
    return __int_as_float(__float_as_int(p) + (k << 23));
}
// 1/y via bit-trick seed + 3 Newton steps (y > 0 normal range)
__device__ __forceinline__ float fast_rcp(float y) {
    float r = __int_as_float(0x7EF311C3 - __float_as_int(y));
    r = r * fmaf(-y, r, 2.0f);
    r = r * fmaf(-y, r, 2.0f);
    r = r * fmaf(-y, r, 2.0f);
    return r;
}
__device__ __forceinline__ float fast_sigmoid(float x) {
    float xc = fminf(fmaxf(x, -80.0f), 80.0f);
    return fast_rcp(1.0f + fast_exp(-xc));
}
__device__ __forceinline__ float fast_tanh(float x) {
    return fmaf(2.0f, fast_sigmoid(2.0f * x), -1.0f);
}

// Grid barrier over one 64-CTA domain: monotone ticket (replay-safe).
__device__ __forceinline__ void grid_barrier(unsigned long long* tick,
                                             unsigned long long& base, int& cnt) {
    __threadfence();
    __syncthreads();
    if (threadIdx.x == 0) {
        if (cnt == 0) {
            unsigned long long v = atomicAdd(tick, 1ull);
            base = (v / NBH) * NBH;
        } else {
            atomicAdd(tick, 1ull);   // fire-and-forget
        }
        cnt++;
        unsigned long long target = base + (unsigned long long)cnt * NBH;
        while (*(volatile unsigned long long*)tick < target) __nanosleep(16);
        __threadfence();
    }
    __syncthreads();
}

// ------------------------- merged prep kernel --------------------------------
__global__ void prep_all(
    const float* __restrict__ Wl, const float* __restrict__ Rl, const float* __restrict__ bl,
    const float* __restrict__ Wc, const float* __restrict__ Rc, const float* __restrict__ bc,
    const float* __restrict__ Wr, const float* __restrict__ Rr, const float* __restrict__ br,
    const float* __restrict__ x)
{
    size_t idx = (size_t)blockIdx.x * 256 + threadIdx.x;
    const size_t NENC  = (size_t)KENC * G4;
    const size_t NRNN  = (size_t)KRNN * G4;
    const size_t NCONV = (size_t)TT * BB * FF;

    if (idx < NENC) {
        size_t k = idx >> 12; int np = (int)(idx & 4095);
        int u = np >> 2, gate = np & 3, col = gate * UU + u;
        float v = (k < FF) ? Wl[k * G4 + col] : Rl[(k - FF) * G4 + col];
        g_Wenc[idx] = __float2half_rn(v);
        return;
    }
    idx -= NENC;
    if (idx < NENC) {
        size_t k = idx >> 12; int np = (int)(idx & 4095);
        int u = np >> 2, gate = np & 3, col = gate * UU + u;
        float v = (k < FF) ? Wc[k * G4 + col] : Rc[(k - FF) * G4 + col];
        g_Wcell[idx] = __float2half_rn(v);
        return;
    }
    idx -= NENC;
    if (idx < NRNN) {
        size_t k = idx >> 12; int np = (int)(idx & 4095);
        int u = np >> 2, gate = np & 3, col = gate * UU + u;
        float v = (k < UU) ? Wr[k * G4 + col] : Rr[(k - UU) * G4 + col];
        g_Wrnn[idx] = __float2half_rn(v);
        return;
    }
    idx -= NRNN;
    if (idx < NCONV) {
        size_t t = idx / (BB * FF);
        int r = (int)(idx % (BB * FF));
        int b = r / FF, f = r % FF;
        g_XF16[idx] = __float2half_rn(x[((size_t)b * TT + t) * FF + f]);
        return;
    }
    idx -= NCONV;
    if (idx < 3 * (size_t)G4) {
        int sel = (int)(idx >> 12), np = (int)(idx & 4095);
        int u = np >> 2, gate = np & 3;
        const float* b = (sel == 0) ? bl : (sel == 1) ? bc : br;
        float* dst = (sel == 0) ? g_benc : (sel == 1) ? g_bcell : g_brnn;
        dst[np] = b[gate * UU + u];
    }
}

// ------------------------- GEMM core (per-group) -----------------------------
__device__ __forceinline__ void mma_chunk(uint32_t bufA, uint32_t bufB,
                                          const uint32_t* offA, const uint32_t* offB,
                                          float acc[2][2][4]) {
#pragma unroll
    for (int kk = 0; kk < 4; kk++) {
        uint32_t af[2][4], bfr[2][2];
#pragma unroll
        for (int mt = 0; mt < 2; mt++) ldsm_x4(af[mt], bufA + offA[kk * 2 + mt]);
#pragma unroll
        for (int nt = 0; nt < 2; nt++) ldsm_x2t(bfr[nt], bufB + offB[kk * 2 + nt]);
#pragma unroll
        for (int mt = 0; mt < 2; mt++)
#pragma unroll
            for (int nt = 0; nt < 2; nt++)
                mma16816(acc[mt][nt], af[mt], bfr[nt]);
    }
}

// One group's GEMM over chunks [cg0, cg0+nchg). A = [A0 (k0g cols) | A1 (UU-stride)].
// B resident (gB==null): chunk c at su + c*8192. Else streamed into sW-region ring.
__device__ __forceinline__ void run_gemm(
    uint32_t su, int g, int tg, int lr, uint32_t o1, uint32_t o2,
    int cg0, int nchg,
    const __half* A0, int lda0, int k0g, const __half* A1,
    const __half* gB, int nbase, int mbase,
    const uint32_t* offA, const uint32_t* offB, float acc[2][2][4],
    int pre)
{
    const int hb = (int)(((uint32_t)tg & 3u) << 4);  // half-col base
    auto issue = [&](int c) {
        int s = (c - cg0) % 3;
        uint32_t bufA = su + SA_OFF + (uint32_t)(g * 3 + s) * 8192;
        int kg = (c << 6) + hb;
        const __half* srcA = (kg < k0g)
            ? A0 + (size_t)(mbase + lr) * lda0 + kg
            : A1 + (size_t)(mbase + lr) * UU + (kg - k0g);
        cp16u(bufA + o1, srcA);
        cp16u(bufA + o2, srcA + 8);
        if (gB) {
            uint32_t bufB = su + (uint32_t)(g * 3 + s) * 8192;
            const __half* srcB = gB + (size_t)((c << 6) + lr) * G4 + nbase + hb;
            cp16u(bufB + o1, srcB);
            cp16u(bufB + o2, srcB + 8);
        }
        cp_commit();
    };

    if (!pre) issue(cg0);
    issue(cg0 + 1);

    const int cend = cg0 + nchg;
    for (int c = cg0; c < cend; c++) {
        if (c < cend - 1) cp_wait<1>();
        else              cp_wait<0>();
        bar_named(1 + g);
        if (c + 2 < cend) issue(c + 2);
        int s = (c - cg0) % 3;
        uint32_t bufA = su + SA_OFF + (uint32_t)(g * 3 + s) * 8192;
        uint32_t bufB = gB ? (su + (uint32_t)(g * 3 + s) * 8192)
                           : (su + (uint32_t)c * 8192);
        mma_chunk(bufA, bufB, offA, offB, acc);
    }
}

// ------------------------- epilogue ------------------------------------------
__device__ __forceinline__ void epilogue(
    char* smem, float acc[2][2][4], const float* sBias, float* cst,
    __half* H16o, __half* H16o2, float* Hf,
    int g, int wm, int wn, int lane, int tid, int mbase, int ub)
{
    bar_named(1 + g);   // group done reading its ring buffers
    float* sCg = (float*)(smem + SA_OFF + g * 24576);
    const int g2 = lane >> 2, t4 = lane & 3;
#pragma unroll
    for (int mt = 0; mt < 2; mt++)
#pragma unroll
        for (int nt = 0; nt < 2; nt++) {
            int r0 = wm * 32 + mt * 16 + g2;
            int c0 = wn * 16 + nt * 8 + 2 * t4;
            sCg[r0 * 68 + c0]           = acc[mt][nt][0];
            sCg[r0 * 68 + c0 + 1]       = acc[mt][nt][1];
            sCg[(r0 + 8) * 68 + c0]     = acc[mt][nt][2];
            sCg[(r0 + 8) * 68 + c0 + 1] = acc[mt][nt][3];
        }
    __syncthreads();
    const float* sC0 = (const float*)(smem + SA_OFF);
    const float* sC1 = (const float*)(smem + SA_OFF + 24576);
    const float4* b4 = (const float4*)sBias;
#pragma unroll
    for (int i = 0; i < 2; i++) {
        int p = tid + (i << 9);
        int bl = p >> 4, ul = p & 15;
        float4 z0 = *(const float4*)&sC0[bl * 68 + ul * 4];
        float4 z1 = *(const float4*)&sC1[bl * 68 + ul * 4];
        float4 bz = b4[ul];
        float zi = z0.x + z1.x + bz.x;
        float zf = z0.y + z1.y + bz.y;
        float zg = z0.z + z1.z + bz.z;
        float zo = z0.w + z1.w + bz.w;
        float cn = fast_sigmoid(zf) * cst[i] + fast_sigmoid(zi) * fast_tanh(zg);
        float h = fast_sigmoid(zo) * fast_tanh(cn);
        cst[i] = cn;
        int idx = (mbase + bl) * UU + ub + ul;
        __half h16 = __float2half_rn(h);
        H16o[idx] = h16;
        if (H16o2) H16o2[idx] = h16;
        if (Hf) Hf[idx] = h;
    }
    __syncthreads();    // gates done reading sC before rings are reused
}

// Dense head for batch row b (512 threads, 16 per unit).
__device__ __forceinline__ void dense_cta(
    int b, int s, const float* hsrc,
    const float* __restrict__ W1, const float* __restrict__ b1,
    const float* __restrict__ W2, const float* __restrict__ b2,
    float* __restrict__ out, float* sRed, int tid)
{
    int j = tid >> 4, l16 = tid & 15;
    float p = 0.0f;
    const float* hb = hsrc + (size_t)b * UU;
    for (int k = l16; k < UU; k += 16) p += __ldcg(&hb[k]) * W1[k * DH + j];
    p += __shfl_xor_sync(0xffffffffu, p, 1);
    p += __shfl_xor_sync(0xffffffffu, p, 2);
    p += __shfl_xor_sync(0xffffffffu, p, 4);
    p += __shfl_xor_sync(0xffffffffu, p, 8);
    if (l16 == 0) sRed[j] = fmaxf(p + b1[j], 0.0f);
    __syncthreads();
    if (tid < FF) {
        float a = b2[tid];
#pragma unroll
        for (int jj = 0; jj < DH; jj++) a += sRed[jj] * W2[jj * FF + tid];
        out[((size_t)b * OUTS + s) * FF + tid] = a;
        g_P16[b * FF + tid] = __float2half_rn(a);
    }
    __syncthreads();
}

__device__ __forceinline__ void zero_acc(float acc[2][2][4]) {
#pragma unroll
    for (int i = 0; i < 2; i++)
#pragma unroll
        for (int j = 0; j < 2; j++)
#pragma unroll
            for (int q = 0; q < 4; q++) acc[i][j][q] = 0.0f;
}

// ------------------------- THE persistent kernel ----------------------------
__global__ void __launch_bounds__(NT, 1) rnn_all(
    const float* __restrict__ W1, const float* __restrict__ b1,
    const float* __restrict__ W2, const float* __restrict__ b2,
    float* __restrict__ out)
{
    extern __shared__ char smem[];
    uint32_t su;
    asm("{ .reg .u64 t; cvta.to.shared.u64 t, %1; cvt.u32.u64 %0, t; }"
        : "=r"(su) : "l"(smem));
    __shared__ float sBias[192];
    __shared__ float sRed[DH];

    const int tid = threadIdx.x, lane = tid & 31, warp = tid >> 5;
    const int g = warp >> 3;                 // k-split group 0/1
    const int wg = warp & 7, wm = wg >> 2, wn = wg & 3;
    const int cta = blockIdx.x;
    const int mbase = (cta & 1) * 64, nbase = (cta >> 1) * 64;
    const int ub = nbase >> 2;
    const int bden = ((cta & 1) << 6) | (cta >> 1);   // dense batch row (own half)
    unsigned long long* tick = &g_tick2[(cta & 1) * 16];
    const int tg = tid & 255;                // thread id within group
    const int lr = tg >> 2;                  // load row 0..63
    const uint32_t bcb = (tg & 3) * 32;      // load byte col
    const uint32_t o1 = SWZ(lr * 128 + bcb);
    const uint32_t o2 = SWZ(lr * 128 + bcb + 16);

    // precomputed swizzled ldsm offsets
    uint32_t offA[8], offB[8];
    {
        const int lrow = lane & 7, lsel = lane >> 3;
#pragma unroll
        for (int kk = 0; kk < 4; kk++) {
#pragma unroll
            for (int mt = 0; mt < 2; mt++) {
                int row = wm * 32 + mt * 16 + lrow + ((lsel & 1) << 3);
                offA[kk * 2 + mt] = SWZ((uint32_t)(row * 128 + kk * 32 + ((lsel >> 1) << 4)));
            }
#pragma unroll
            for (int nt = 0; nt < 2; nt++) {
                int row = kk * 16 + (lane & 15);
                offB[kk * 2 + nt] = SWZ((uint32_t)(row * 128 + wn * 32 + nt * 16));
            }
        }
    }

    unsigned long long bar_base = 0ull;
    int bar_cnt = 0;

    if (tid < 64) {
        sBias[tid]       = g_benc[nbase + tid];
        sBias[64 + tid]  = g_bcell[nbase + tid];
        sBias[128 + tid] = g_brnn[nbase + tid];
    }
    // zero h0 slice
    if (tid < 128) {
        uint4 z = {0, 0, 0, 0};
        ((uint4*)g_H16[0])[cta * 128 + tid] = z;
    }
    // resident encoder weights: 17 chunks x 64 rows x 8 x 16B
    for (int i = tid; i < 17 * 512; i += NT) {
        int c = i >> 9, r = (i >> 3) & 63, u = i & 7;
        cp16u(su + (uint32_t)c * 8192 + SWZ((uint32_t)(r * 128 + u * 16)),
              g_Wenc + (size_t)(c * 64 + r) * G4 + nbase + u * 8);
    }
    cp_commit();
    cp_wait<0>();
    __syncthreads();

    // pre-issue x_0 chunk (group 0, stage 0)
    if (g == 0) {
        const __half* src = g_XF16 + (size_t)(mbase + lr) * FF + (bcb >> 1);
        cp16u(su + SA_OFF + o1, src);
        cp16u(su + SA_OFF + o2, src + 8);
        cp_commit();
    }

    float cl[2] = {0, 0}, cr[2];
    grid_barrier(tick, bar_base, bar_cnt);

    float acc[2][2][4];
    const int cg0e = g ? 9 : 0, nchge = g ? 8 : 9;   // enc/lstm split of 17
    const int cg0r = g ? 16 : 0;                      // rnn split of 32

    // ---------------- encoder: 256 steps ----------------
#pragma unroll 1
    for (int t = 0; t < TT; t++) {
        zero_acc(acc);
        run_gemm(su, g, tg, lr, o1, o2, cg0e, nchge,
                 g_XF16 + (size_t)t * BB * FF, FF, FF, g_H16[t & 1],
                 nullptr, nbase, mbase, offA, offB, acc, (g == 0) ? 1 : 0);
        bool last = (t == TT - 1);
        epilogue(smem, acc, sBias, cl,
                 g_H16[(t + 1) & 1],
                 last ? g_HR16[0] : nullptr,
                 last ? g_Hl : nullptr,
                 g, wm, wn, lane, tid, mbase, ub);
        if (!last && g == 0) {
            const __half* src = g_XF16 + (size_t)(t + 1) * BB * FF
                              + (size_t)(mbase + lr) * FF + (bcb >> 1);
            cp16u(su + SA_OFF + o1, src);
            cp16u(su + SA_OFF + o2, src + 8);
            cp_commit();
        }
        grid_barrier(tick, bar_base, bar_cnt);
    }
    cr[0] = cl[0]; cr[1] = cl[1];

    // pred0 = dense(encoder h)
    dense_cta(bden, 0, g_Hl, W1, b1, W2, b2, out, sRed, tid);
    grid_barrier(tick, bar_base, bar_cnt);

    // ---------------- decoder: 31 steps (weights streamed via sW-region rings)
#pragma unroll 1
    for (int s = 1; s < OUTS; s++) {
        // lstm_cell: A = [pred | hl], B = Wcell streamed
        zero_acc(acc);
        run_gemm(su, g, tg, lr, o1, o2, cg0e, nchge,
                 g_P16, FF, FF, g_H16[(s + 1) & 1],
                 g_Wcell, nbase, mbase, offA, offB, acc, 0);
        epilogue(smem, acc, sBias + 64, cl,
                 g_H16[s & 1], nullptr, nullptr,
                 g, wm, wn, lane, tid, mbase, ub);
        grid_barrier(tick, bar_base, bar_cnt);

        // rnn_cell: A = [hl | hr], B = Wrnn streamed
        zero_acc(acc);
        run_gemm(su, g, tg, lr, o1, o2, cg0r, 16,
                 g_H16[s & 1], UU, UU, g_HR16[(s + 1) & 1],
                 g_Wrnn, nbase, mbase, offA, offB, acc, 0);
        epilogue(smem, acc, sBias + 128, cr,
                 g_HR16[s & 1], nullptr, g_Hr,
                 g, wm, wn, lane, tid, mbase, ub);
        grid_barrier(tick, bar_base, bar_cnt);

        dense_cta(bden, s, g_Hr, W1, b1, W2, b2, out, sRed, tid);
        grid_barrier(tick, bar_base, bar_cnt);
    }
}

// ------------------------- launcher -----------------------------------------
extern "C" void kernel_launch(void* const* d_in, const int* in_sizes, int n_in,
                              void* d_out, int out_size) {
    const float* inputs = (const float*)d_in[0];
    const float* Wl = (const float*)d_in[1];
    const float* Rl = (const float*)d_in[2];
    const float* bl = (const float*)d_in[3];
    const float* Wc = (const float*)d_in[4];
    const float* Rc = (const float*)d_in[5];
    const float* bc = (const float*)d_in[6];
    const float* Wr = (const float*)d_in[7];
    const float* Rr = (const float*)d_in[8];
    const float* br = (const float*)d_in[9];
    const float* W1 = (const float*)d_in[10];
    const float* b1 = (const float*)d_in[11];
    const float* W2 = (const float*)d_in[12];
    const float* b2 = (const float*)d_in[13];
    float* out = (float*)d_out;

    cudaFuncSetAttribute(rnn_all, cudaFuncAttributeMaxDynamicSharedMemorySize,
                         DYN_BYTES);

    size_t total = 2 * (size_t)KENC * G4 + (size_t)KRNN * G4
                 + (size_t)TT * BB * FF + 3 * (size_t)G4;
    prep_all<<<(int)((total + 255) / 256), 256>>>(Wl, Rl, bl, Wc, Rc, bc,
                                                  Wr, Rr, br, inputs);

    rnn_all<<<NB, NT, DYN_BYTES>>>(W1, b1, W2, b2, out);
}